// round 9
// baseline (speedup 1.0000x reference)
#include <cuda_runtime.h>
#include <cstdint>

#define HW 1024
#define BATCH 8

__device__ float g_cat [BATCH * 1024 * HW];
__device__ float g_z   [BATCH * 256  * HW];
__device__ float g_qkv [BATCH * 768  * HW];   // holds tf32 BITS after qkv pack
__device__ float g_att [BATCH * 256  * HW];
__device__ float g_w3  [2 * 9 * 256 * 256];   // [i][t][co][ci]
__device__ float g_part[3 * BATCH * 256 * HW];

// ---------------------------------------------------------------------------
__device__ __forceinline__ uint32_t f2tf(float x) {
    uint32_t r;
    asm("cvt.rna.tf32.f32 %0, %1;" : "=r"(r) : "f"(x));
    return r;
}

__device__ __forceinline__ void mma8(float c[4],
    uint32_t a0, uint32_t a1, uint32_t a2, uint32_t a3,
    uint32_t b0, uint32_t b1)
{
    asm volatile(
        "mma.sync.aligned.m16n8k8.row.col.f32.tf32.tf32.f32 "
        "{%0,%1,%2,%3}, {%4,%5,%6,%7}, {%8,%9}, {%0,%1,%2,%3};"
        : "+f"(c[0]), "+f"(c[1]), "+f"(c[2]), "+f"(c[3])
        : "r"(a0), "r"(a1), "r"(a2), "r"(a3), "r"(b0), "r"(b1));
}

#define AST 36
#define BST 136

// ---------------------------------------------------------------------------
__global__ void reorder_w3_kernel(const float* __restrict__ w, float* __restrict__ o)
{
    int idx = blockIdx.x * 256 + threadIdx.x;
    if (idx >= 2 * 9 * 65536) return;
    int i  = idx / (9 * 65536);
    int r  = idx % (9 * 65536);
    int t  = r / 65536;
    int rc = r % 65536;
    int co = rc >> 8, ci = rc & 255;
    o[idx] = w[((long)(i * 256 + co) * 256 + ci) * 9 + t];
}

// ---------------------------------------------------------------------------
__device__ __forceinline__ void mma_chunk(
    const uint32_t* __restrict__ As, const uint32_t* __restrict__ Bs,
    int wm, int wn, int lane, float acc[4][4][4])
{
    #pragma unroll
    for (int ks = 0; ks < 4; ks++) {
        uint32_t a[4][4], bb[4][2];
        int ar = wm * 64 + (lane >> 2);
        int ac = ks * 8 + (lane & 3);
        #pragma unroll
        for (int mt = 0; mt < 4; mt++) {
            int r = ar + mt * 16;
            a[mt][0] = As[r * AST + ac];
            a[mt][1] = As[(r + 8) * AST + ac];
            a[mt][2] = As[r * AST + ac + 4];
            a[mt][3] = As[(r + 8) * AST + ac + 4];
        }
        int br = ks * 8 + (lane & 3);
        int bc = wn * 32 + (lane >> 2);
        #pragma unroll
        for (int nt = 0; nt < 4; nt++) {
            bb[nt][0] = Bs[br * BST + bc + nt * 8];
            bb[nt][1] = Bs[(br + 4) * BST + bc + nt * 8];
        }
        #pragma unroll
        for (int mt = 0; mt < 4; mt++)
            #pragma unroll
            for (int nt = 0; nt < 4; nt++)
                mma8(acc[mt][nt], a[mt][0], a[mt][1], a[mt][2], a[mt][3],
                     bb[nt][0], bb[nt][1]);
    }
}

// ---------------------------------------------------------------------------
// tf32 GEMM for 1x1 convs.
// flags: 1=BN, 2=SiLU, 4=residual, 8=qkv-pack (bn=rw, res=rh; outputs tf32
//        bits with positional bias pre-added to K channels [256,512)).
// ---------------------------------------------------------------------------
__global__ __launch_bounds__(256) void gemm_tf32_kernel(
    const float* __restrict__ X, const float* __restrict__ W,
    const float* __restrict__ bn, const float* __restrict__ res,
    float* __restrict__ out,
    int Cin, int Cout, long xbS, long obS, long rbS, int flags)
{
    __shared__ uint32_t As[128 * AST];
    __shared__ uint32_t Bs[32 * BST];

    const int b   = blockIdx.z;
    const int p0  = blockIdx.x * 128;
    const int co0 = blockIdx.y * 128;
    const int tid = threadIdx.x;
    const int lane = tid & 31, wid = tid >> 5;
    const int wm = wid >> 2, wn = wid & 3;

    const float* Xb = X + (long)b * xbS;

    float acc[4][4][4];
    #pragma unroll
    for (int mt = 0; mt < 4; mt++)
        #pragma unroll
        for (int nt = 0; nt < 4; nt++)
            #pragma unroll
            for (int e = 0; e < 4; e++) acc[mt][nt][e] = 0.f;

    for (int k0 = 0; k0 < Cin; k0 += 32) {
        #pragma unroll
        for (int it = 0; it < 4; it++) {
            int r = (tid >> 3) + it * 32;
            int c = (tid & 7) * 4;
            float4 v = *(const float4*)&W[(long)(co0 + r) * Cin + k0 + c];
            As[r * AST + c + 0] = f2tf(v.x);
            As[r * AST + c + 1] = f2tf(v.y);
            As[r * AST + c + 2] = f2tf(v.z);
            As[r * AST + c + 3] = f2tf(v.w);
        }
        #pragma unroll
        for (int it = 0; it < 4; it++) {
            int kk = (tid >> 5) + it * 8;
            int pp = lane * 4;
            float4 v = *(const float4*)&Xb[(long)(k0 + kk) * HW + p0 + pp];
            Bs[kk * BST + pp + 0] = f2tf(v.x);
            Bs[kk * BST + pp + 1] = f2tf(v.y);
            Bs[kk * BST + pp + 2] = f2tf(v.z);
            Bs[kk * BST + pp + 3] = f2tf(v.w);
        }
        __syncthreads();
        mma_chunk(As, Bs, wm, wn, lane, acc);
        __syncthreads();
    }

    if (flags & 8) {
        // qkv pack: K channels get rw+rh bias; everything stored as tf32 bits
        const float* rw = bn;
        const float* rh = res;
        float* ob = out + (long)b * obS;
        #pragma unroll
        for (int mt = 0; mt < 4; mt++) {
            int r0 = co0 + wm * 64 + mt * 16 + (lane >> 2);
            int r1 = r0 + 8;
            bool k0r = (r0 >= 256 && r0 < 512);
            bool k1r = (r1 >= 256 && r1 < 512);
            const float* rw0 = rw + (((r0 - 256) >> 6) * 64 + (r0 & 63)) * 32;
            const float* rh0 = rh + (((r0 - 256) >> 6) * 64 + (r0 & 63)) * 32;
            const float* rw1 = rw + (((r1 - 256) >> 6) * 64 + (r1 & 63)) * 32;
            const float* rh1 = rh + (((r1 - 256) >> 6) * 64 + (r1 & 63)) * 32;
            #pragma unroll
            for (int nt = 0; nt < 4; nt++) {
                int col = p0 + wn * 32 + nt * 8 + 2 * (lane & 3);
                float v00 = acc[mt][nt][0];
                float v01 = acc[mt][nt][1];
                float v10 = acc[mt][nt][2];
                float v11 = acc[mt][nt][3];
                if (k0r) {
                    v00 += rw0[col & 31] + rh0[col >> 5];
                    v01 += rw0[(col + 1) & 31] + rh0[(col + 1) >> 5];
                }
                if (k1r) {
                    v10 += rw1[col & 31] + rh1[col >> 5];
                    v11 += rw1[(col + 1) & 31] + rh1[(col + 1) >> 5];
                }
                *(float2*)&ob[(long)r0 * HW + col] = make_float2(
                    __uint_as_float(f2tf(v00)), __uint_as_float(f2tf(v01)));
                *(float2*)&ob[(long)r1 * HW + col] = make_float2(
                    __uint_as_float(f2tf(v10)), __uint_as_float(f2tf(v11)));
            }
        }
        return;
    }

    #pragma unroll
    for (int mt = 0; mt < 4; mt++) {
        int r0 = co0 + wm * 64 + mt * 16 + (lane >> 2);
        int r1 = r0 + 8;
        float s0 = 1.f, c0 = 0.f, s1 = 1.f, c1 = 0.f;
        if (flags & 1) {
            float g0 = bn[r0], b0v = bn[Cout + r0], m0 = bn[2*Cout + r0], v0 = bn[3*Cout + r0];
            s0 = g0 * rsqrtf(v0 + 1e-3f); c0 = b0v - m0 * s0;
            float g1 = bn[r1], b1v = bn[Cout + r1], m1 = bn[2*Cout + r1], v1 = bn[3*Cout + r1];
            s1 = g1 * rsqrtf(v1 + 1e-3f); c1 = b1v - m1 * s1;
        }
        #pragma unroll
        for (int nt = 0; nt < 4; nt++) {
            int col = p0 + wn * 32 + nt * 8 + 2 * (lane & 3);
            float v00 = acc[mt][nt][0] * s0 + c0;
            float v01 = acc[mt][nt][1] * s0 + c0;
            float v10 = acc[mt][nt][2] * s1 + c1;
            float v11 = acc[mt][nt][3] * s1 + c1;
            if (flags & 2) {
                v00 = v00 / (1.f + __expf(-v00));
                v01 = v01 / (1.f + __expf(-v01));
                v10 = v10 / (1.f + __expf(-v10));
                v11 = v11 / (1.f + __expf(-v11));
            }
            if (flags & 4) {
                const float* rb = res + (long)b * rbS;
                v00 += rb[(long)r0 * HW + col];
                v01 += rb[(long)r0 * HW + col + 1];
                v10 += rb[(long)r1 * HW + col];
                v11 += rb[(long)r1 * HW + col + 1];
            }
            float* ob = out + (long)b * obS;
            *(float2*)&ob[(long)r0 * HW + col] = make_float2(v00, v01);
            *(float2*)&ob[(long)r1 * HW + col] = make_float2(v10, v11);
        }
    }
}

// ---------------------------------------------------------------------------
// Tap-split tf32 3x3 conv (unchanged from round 8).
// ---------------------------------------------------------------------------
__global__ __launch_bounds__(256) void conv3_part_kernel(
    const float* __restrict__ X, const float* __restrict__ Wt,
    float* __restrict__ part_out, long xbS)
{
    __shared__ uint32_t As[128 * AST];
    __shared__ uint32_t Bs[32 * BST];

    const int b    = blockIdx.z;
    const int p0   = blockIdx.x * 128;
    const int part = blockIdx.y >> 1;
    const int co0  = (blockIdx.y & 1) * 128;
    const int tid  = threadIdx.x;
    const int lane = tid & 31, wid = tid >> 5;
    const int wm = wid >> 2, wn = wid & 3;

    const float* Xb = X + (long)b * xbS;

    float acc[4][4][4];
    #pragma unroll
    for (int mt = 0; mt < 4; mt++)
        #pragma unroll
        for (int nt = 0; nt < 4; nt++)
            #pragma unroll
            for (int e = 0; e < 4; e++) acc[mt][nt][e] = 0.f;

    for (int c = 0; c < 24; c++) {
        const int t  = part * 3 + (c >> 3);
        const int kc = (c & 7) * 32;
        const int dy = t / 3 - 1, dx = t % 3 - 1;
        const float* Wtt = Wt + t * 65536;

        #pragma unroll
        for (int it = 0; it < 4; it++) {
            int r = (tid >> 3) + it * 32;
            int cc = (tid & 7) * 4;
            float4 v = *(const float4*)&Wtt[(long)(co0 + r) * 256 + kc + cc];
            As[r * AST + cc + 0] = f2tf(v.x);
            As[r * AST + cc + 1] = f2tf(v.y);
            As[r * AST + cc + 2] = f2tf(v.z);
            As[r * AST + cc + 3] = f2tf(v.w);
        }
        #pragma unroll
        for (int e = tid; e < 4096; e += 256) {
            int kk = e >> 7, p = e & 127;
            int pix = p0 + p;
            int row = (pix >> 5) + dy;
            int col = (pix & 31) + dx;
            float xv = 0.f;
            if ((unsigned)row < 32u && (unsigned)col < 32u)
                xv = Xb[(long)(kc + kk) * HW + row * 32 + col];
            Bs[kk * BST + p] = f2tf(xv);
        }
        __syncthreads();
        mma_chunk(As, Bs, wm, wn, lane, acc);
        __syncthreads();
    }

    float* ob = part_out + ((long)part * BATCH + b) * 256 * HW;
    #pragma unroll
    for (int mt = 0; mt < 4; mt++) {
        int r0 = co0 + wm * 64 + mt * 16 + (lane >> 2);
        int r1 = r0 + 8;
        #pragma unroll
        for (int nt = 0; nt < 4; nt++) {
            int col = p0 + wn * 32 + nt * 8 + 2 * (lane & 3);
            *(float2*)&ob[(long)r0 * HW + col] =
                make_float2(acc[mt][nt][0], acc[mt][nt][1]);
            *(float2*)&ob[(long)r1 * HW + col] =
                make_float2(acc[mt][nt][2], acc[mt][nt][3]);
        }
    }
}

// ---------------------------------------------------------------------------
__global__ void tap_reduce_kernel(const float* __restrict__ part,
                                  const float* __restrict__ bn,
                                  float* __restrict__ out)
{
    const long PS = (long)BATCH * 256 * HW;
    long idx = (long)blockIdx.x * 256 + threadIdx.x;
    if (idx >= PS / 4) return;
    long e = idx * 4;
    int ch = (int)((e / HW) & 255);

    float4 a = *(const float4*)&part[e];
    float4 b4 = *(const float4*)&part[PS + e];
    float4 c4 = *(const float4*)&part[2 * PS + e];

    float g = bn[ch], bb = bn[256 + ch], mu = bn[512 + ch], vv = bn[768 + ch];
    float s = g * rsqrtf(vv + 1e-3f);
    float c = bb - mu * s;

    float v[4] = {a.x + b4.x + c4.x, a.y + b4.y + c4.y,
                  a.z + b4.z + c4.z, a.w + b4.w + c4.w};
    #pragma unroll
    for (int i = 0; i < 4; i++) {
        float t = v[i] * s + c;
        v[i] = t / (1.f + __expf(-t));
    }
    *(float4*)&out[e] = make_float4(v[0], v[1], v[2], v[3]);
}

// ---------------------------------------------------------------------------
// tf32 flash attention. qkv buffer now holds PRE-CONVERTED tf32 bits with the
// positional bias already folded into K -> fills are pure uint4 bit-copies.
// ---------------------------------------------------------------------------
#define QST 72
#define VST 68
#define FA_Q   0
#define FA_KR  (64 * QST)
#define FA_V   (FA_KR + 64 * QST)
#define FA_P   (FA_V + 64 * VST)
#define FA_RED (FA_P + 64 * VST)
#define FA_TOT (FA_RED + 256)

extern __shared__ uint32_t fa_u[];

__global__ __launch_bounds__(256) void flash_tf32_kernel(
    const uint32_t* __restrict__ qkv, float* __restrict__ out)
{
    uint32_t* Qs  = fa_u + FA_Q;
    uint32_t* KRs = fa_u + FA_KR;
    uint32_t* Vs  = fa_u + FA_V;
    uint32_t* Ps  = fa_u + FA_P;
    float* red_max = (float*)(fa_u + FA_RED);
    float* red_sum = red_max + 128;

    const int b  = blockIdx.z;
    const int h  = blockIdx.y;
    const int i0 = blockIdx.x * 64;
    const int tid  = threadIdx.x;
    const int lane = tid & 31, wid = tid >> 5;
    const int wm = wid >> 1;
    const int wn = wid & 1;
    const int lq = lane >> 2;
    const int lr = lane & 3;

    const uint32_t* qb = qkv + ((long)b * 768 + h * 64) * HW;
    const uint32_t* kb = qb + 256 * HW;
    const uint32_t* vb = qb + 512 * HW;

    // Q tile: pure bit copy (tf32 already)
    #pragma unroll
    for (int it = 0; it < 4; it++) {
        int idx = tid + it * 256;          // 0..1023 u4 elems
        int d = idx >> 4, i4 = (idx & 15) * 4;
        *(uint4*)&Qs[d * QST + i4] = *(const uint4*)&qb[(long)d * HW + i0 + i4];
    }

    const int row_lo = wm * 16 + lq;
    const int row_hi = row_lo + 8;

    float m_lo = -1e30f, m_hi = -1e30f, l_lo = 0.f, l_hi = 0.f;
    float accO[4][4];
    #pragma unroll
    for (int nt = 0; nt < 4; nt++)
        #pragma unroll
        for (int e = 0; e < 4; e++) accO[nt][e] = 0.f;

    __syncthreads();

    for (int j0 = 0; j0 < HW; j0 += 64) {
        // KR + V tiles: vector bit copies
        #pragma unroll
        for (int it = 0; it < 4; it++) {
            int idx = tid + it * 256;
            int d = idx >> 4, j4 = (idx & 15) * 4;
            *(uint4*)&KRs[d * QST + j4] = *(const uint4*)&kb[(long)d * HW + j0 + j4];
            *(uint4*)&Vs[d * VST + j4]  = *(const uint4*)&vb[(long)d * HW + j0 + j4];
        }
        __syncthreads();

        float s[4][4];
        #pragma unroll
        for (int nt = 0; nt < 4; nt++)
            #pragma unroll
            for (int e = 0; e < 4; e++) s[nt][e] = 0.f;

        #pragma unroll
        for (int ks = 0; ks < 8; ks++) {
            int d0 = ks * 8 + lr;
            uint32_t a0 = Qs[d0 * QST + row_lo];
            uint32_t a1 = Qs[d0 * QST + row_hi];
            uint32_t a2 = Qs[(d0 + 4) * QST + row_lo];
            uint32_t a3 = Qs[(d0 + 4) * QST + row_hi];
            #pragma unroll
            for (int nt = 0; nt < 4; nt++) {
                int jc = wn * 32 + nt * 8 + lq;
                uint32_t b0 = KRs[d0 * QST + jc];
                uint32_t b1 = KRs[(d0 + 4) * QST + jc];
                mma8(s[nt], a0, a1, a2, a3, b0, b1);
            }
        }

        #pragma unroll
        for (int nt = 0; nt < 4; nt++)
            #pragma unroll
            for (int e = 0; e < 4; e++) s[nt][e] *= 0.125f;

        float mx_lo = -1e30f, mx_hi = -1e30f;
        #pragma unroll
        for (int nt = 0; nt < 4; nt++) {
            mx_lo = fmaxf(mx_lo, fmaxf(s[nt][0], s[nt][1]));
            mx_hi = fmaxf(mx_hi, fmaxf(s[nt][2], s[nt][3]));
        }
        mx_lo = fmaxf(mx_lo, __shfl_xor_sync(0xffffffffu, mx_lo, 1));
        mx_lo = fmaxf(mx_lo, __shfl_xor_sync(0xffffffffu, mx_lo, 2));
        mx_hi = fmaxf(mx_hi, __shfl_xor_sync(0xffffffffu, mx_hi, 1));
        mx_hi = fmaxf(mx_hi, __shfl_xor_sync(0xffffffffu, mx_hi, 2));
        if (lr == 0) {
            red_max[wn * 64 + row_lo] = mx_lo;
            red_max[wn * 64 + row_hi] = mx_hi;
        }
        __syncthreads();
        mx_lo = fmaxf(mx_lo, red_max[(1 - wn) * 64 + row_lo]);
        mx_hi = fmaxf(mx_hi, red_max[(1 - wn) * 64 + row_hi]);

        float mn_lo = fmaxf(m_lo, mx_lo);
        float mn_hi = fmaxf(m_hi, mx_hi);
        float cr_lo = __expf(m_lo - mn_lo);
        float cr_hi = __expf(m_hi - mn_hi);
        m_lo = mn_lo; m_hi = mn_hi;

        float rs_lo = 0.f, rs_hi = 0.f;
        #pragma unroll
        for (int nt = 0; nt < 4; nt++) {
            float p0 = __expf(s[nt][0] - mn_lo);
            float p1 = __expf(s[nt][1] - mn_lo);
            float p2 = __expf(s[nt][2] - mn_hi);
            float p3 = __expf(s[nt][3] - mn_hi);
            rs_lo += p0 + p1;
            rs_hi += p2 + p3;
            int colb = wn * 32 + nt * 8 + 2 * lr;
            *(uint2*)&Ps[row_lo * VST + colb] = make_uint2(f2tf(p0), f2tf(p1));
            *(uint2*)&Ps[row_hi * VST + colb] = make_uint2(f2tf(p2), f2tf(p3));
        }
        rs_lo += __shfl_xor_sync(0xffffffffu, rs_lo, 1);
        rs_lo += __shfl_xor_sync(0xffffffffu, rs_lo, 2);
        rs_hi += __shfl_xor_sync(0xffffffffu, rs_hi, 1);
        rs_hi += __shfl_xor_sync(0xffffffffu, rs_hi, 2);
        if (lr == 0) {
            red_sum[wn * 64 + row_lo] = rs_lo;
            red_sum[wn * 64 + row_hi] = rs_hi;
        }
        __syncthreads();
        rs_lo += red_sum[(1 - wn) * 64 + row_lo];
        rs_hi += red_sum[(1 - wn) * 64 + row_hi];
        l_lo = l_lo * cr_lo + rs_lo;
        l_hi = l_hi * cr_hi + rs_hi;

        #pragma unroll
        for (int nt = 0; nt < 4; nt++) {
            accO[nt][0] *= cr_lo; accO[nt][1] *= cr_lo;
            accO[nt][2] *= cr_hi; accO[nt][3] *= cr_hi;
        }

        #pragma unroll
        for (int ks = 0; ks < 8; ks++) {
            int jj = ks * 8 + lr;
            uint32_t a0 = Ps[row_lo * VST + jj];
            uint32_t a1 = Ps[row_hi * VST + jj];
            uint32_t a2 = Ps[row_lo * VST + jj + 4];
            uint32_t a3 = Ps[row_hi * VST + jj + 4];
            #pragma unroll
            for (int nt = 0; nt < 4; nt++) {
                int dc = wn * 32 + nt * 8 + lq;
                uint32_t b0 = Vs[dc * VST + jj];
                uint32_t b1 = Vs[dc * VST + jj + 4];
                mma8(accO[nt], a0, a1, a2, a3, b0, b1);
            }
        }
        __syncthreads();
    }

    float inv_lo = 1.f / l_lo;
    float inv_hi = 1.f / l_hi;
    float* ob = out + ((long)b * 256 + h * 64) * HW + i0;
    #pragma unroll
    for (int nt = 0; nt < 4; nt++) {
        int d = wn * 32 + nt * 8 + 2 * lr;
        ob[(long)d * HW + row_lo]       = accO[nt][0] * inv_lo;
        ob[(long)(d + 1) * HW + row_lo] = accO[nt][1] * inv_lo;
        ob[(long)d * HW + row_hi]       = accO[nt][2] * inv_hi;
        ob[(long)(d + 1) * HW + row_hi] = accO[nt][3] * inv_hi;
    }
}

// ---------------------------------------------------------------------------
extern "C" void kernel_launch(void* const* d_in, const int* in_sizes, int n_in,
                              void* d_out, int out_size)
{
    const float* x        = (const float*)d_in[0];
    const float* cv1_w    = (const float*)d_in[1];
    const float* cv1_bn   = (const float*)d_in[2];
    const float* cv2_w    = (const float*)d_in[3];
    const float* cv2_bn   = (const float*)d_in[4];
    const float* m_cv1_w  = (const float*)d_in[5];
    const float* m_cv1_bn = (const float*)d_in[6];
    const float* m_qkv_w  = (const float*)d_in[7];
    const float* m_rw     = (const float*)d_in[8];
    const float* m_rh     = (const float*)d_in[9];
    const float* m_cv2_w  = (const float*)d_in[10];
    const float* m_cv2_bn = (const float*)d_in[11];
    float* out = (float*)d_out;

    float *cat, *z, *qkv, *att, *w3, *part;
    cudaGetSymbolAddress((void**)&cat,  g_cat);
    cudaGetSymbolAddress((void**)&z,    g_z);
    cudaGetSymbolAddress((void**)&qkv,  g_qkv);
    cudaGetSymbolAddress((void**)&att,  g_att);
    cudaGetSymbolAddress((void**)&w3,   g_w3);
    cudaGetSymbolAddress((void**)&part, g_part);

    const int FA_SMEM = FA_TOT * 4;
    cudaFuncSetAttribute(flash_tf32_kernel,
                         cudaFuncAttributeMaxDynamicSharedMemorySize, FA_SMEM);

    const long CAT_S = 1024L * HW;
    const long RED_N = (long)BATCH * 256 * HW / 4;

    reorder_w3_kernel<<<(2 * 9 * 65536 + 255) / 256, 256>>>(m_cv1_w, w3);

    // cv1: x (512) -> cat[0:512)
    gemm_tf32_kernel<<<dim3(8, 4, BATCH), 256>>>(
        x, cv1_w, cv1_bn, nullptr, cat,
        512, 512, 512L * HW, CAT_S, 0, 3);

    for (int i = 0; i < 2; i++) {
        const float* yin = cat + (long)(256 + i * 256) * HW;

        conv3_part_kernel<<<dim3(8, 6, BATCH), 256>>>(
            yin, w3 + (long)i * 9 * 65536, part, CAT_S);
        tap_reduce_kernel<<<(int)((RED_N + 255) / 256), 256>>>(
            part, m_cv1_bn + i * 4 * 256, z);

        // qkv 1x1 + attention pack (bias into K, all outputs as tf32 bits)
        gemm_tf32_kernel<<<dim3(8, 6, BATCH), 256>>>(
            z, m_qkv_w + (long)i * 768 * 256,
            m_rw + i * 8192, m_rh + i * 8192, qkv,
            256, 768, 256L * HW, 768L * HW, 0, 8);

        flash_tf32_kernel<<<dim3(16, 4, BATCH), 256, FA_SMEM>>>(
            (const uint32_t*)qkv, att);

        gemm_tf32_kernel<<<dim3(8, 2, BATCH), 256>>>(
            att, m_cv2_w + (long)i * 256 * 256, m_cv2_bn + i * 4 * 256,
            yin, cat + (long)(512 + i * 256) * HW,
            256, 256, 256L * HW, CAT_S, CAT_S, 7);
    }

    gemm_tf32_kernel<<<dim3(8, 4, BATCH), 256>>>(
        cat, cv2_w, cv2_bn, nullptr, out,
        1024, 512, CAT_S, 512L * HW, 0, 3);
}

// round 10
// speedup vs baseline: 1.6398x; 1.6398x over previous
#include <cuda_runtime.h>
#include <cstdint>

#define HW 1024
#define BATCH 8

__device__ float g_cat [BATCH * 1024 * HW];
__device__ float g_z   [BATCH * 256  * HW];
__device__ float g_qkv [BATCH * 768  * HW];    // raw fp32 qkv conv output
__device__ float g_qkvp[BATCH * 768  * HW];    // packed tf32 bits (K has bias)
__device__ float g_att [BATCH * 256  * HW];
__device__ float g_w3  [2 * 9 * 256 * 256];    // [i][t][co][ci]
__device__ float g_part[3 * BATCH * 256 * HW];

// ---------------------------------------------------------------------------
__device__ __forceinline__ uint32_t f2tf(float x) {
    uint32_t r;
    asm("cvt.rna.tf32.f32 %0, %1;" : "=r"(r) : "f"(x));
    return r;
}

__device__ __forceinline__ void mma8(float c[4],
    uint32_t a0, uint32_t a1, uint32_t a2, uint32_t a3,
    uint32_t b0, uint32_t b1)
{
    asm volatile(
        "mma.sync.aligned.m16n8k8.row.col.f32.tf32.tf32.f32 "
        "{%0,%1,%2,%3}, {%4,%5,%6,%7}, {%8,%9}, {%0,%1,%2,%3};"
        : "+f"(c[0]), "+f"(c[1]), "+f"(c[2]), "+f"(c[3])
        : "r"(a0), "r"(a1), "r"(a2), "r"(a3), "r"(b0), "r"(b1));
}

#define AST 36
#define BST 136

// ---------------------------------------------------------------------------
__global__ void reorder_w3_kernel(const float* __restrict__ w, float* __restrict__ o)
{
    int idx = blockIdx.x * 256 + threadIdx.x;
    if (idx >= 2 * 9 * 65536) return;
    int i  = idx / (9 * 65536);
    int r  = idx % (9 * 65536);
    int t  = r / 65536;
    int rc = r % 65536;
    int co = rc >> 8, ci = rc & 255;
    o[idx] = w[((long)(i * 256 + co) * 256 + ci) * 9 + t];
}

// ---------------------------------------------------------------------------
__device__ __forceinline__ void mma_chunk(
    const uint32_t* __restrict__ As, const uint32_t* __restrict__ Bs,
    int wm, int wn, int lane, float acc[4][4][4])
{
    #pragma unroll
    for (int ks = 0; ks < 4; ks++) {
        uint32_t a[4][4], bb[4][2];
        int ar = wm * 64 + (lane >> 2);
        int ac = ks * 8 + (lane & 3);
        #pragma unroll
        for (int mt = 0; mt < 4; mt++) {
            int r = ar + mt * 16;
            a[mt][0] = As[r * AST + ac];
            a[mt][1] = As[(r + 8) * AST + ac];
            a[mt][2] = As[r * AST + ac + 4];
            a[mt][3] = As[(r + 8) * AST + ac + 4];
        }
        int br = ks * 8 + (lane & 3);
        int bc = wn * 32 + (lane >> 2);
        #pragma unroll
        for (int nt = 0; nt < 4; nt++) {
            bb[nt][0] = Bs[br * BST + bc + nt * 8];
            bb[nt][1] = Bs[(br + 4) * BST + bc + nt * 8];
        }
        #pragma unroll
        for (int mt = 0; mt < 4; mt++)
            #pragma unroll
            for (int nt = 0; nt < 4; nt++)
                mma8(acc[mt][nt], a[mt][0], a[mt][1], a[mt][2], a[mt][3],
                     bb[nt][0], bb[nt][1]);
    }
}

// ---------------------------------------------------------------------------
// tf32 GEMM for 1x1 convs (exact R8 version).
// flags: 1=BN, 2=SiLU, 4=residual.
// ---------------------------------------------------------------------------
__global__ __launch_bounds__(256) void gemm_tf32_kernel(
    const float* __restrict__ X, const float* __restrict__ W,
    const float* __restrict__ bn, const float* __restrict__ res,
    float* __restrict__ out,
    int Cin, int Cout, long xbS, long obS, long rbS, int flags)
{
    __shared__ uint32_t As[128 * AST];
    __shared__ uint32_t Bs[32 * BST];

    const int b   = blockIdx.z;
    const int p0  = blockIdx.x * 128;
    const int co0 = blockIdx.y * 128;
    const int tid = threadIdx.x;
    const int lane = tid & 31, wid = tid >> 5;
    const int wm = wid >> 2, wn = wid & 3;

    const float* Xb = X + (long)b * xbS;

    float acc[4][4][4];
    #pragma unroll
    for (int mt = 0; mt < 4; mt++)
        #pragma unroll
        for (int nt = 0; nt < 4; nt++)
            #pragma unroll
            for (int e = 0; e < 4; e++) acc[mt][nt][e] = 0.f;

    for (int k0 = 0; k0 < Cin; k0 += 32) {
        #pragma unroll
        for (int it = 0; it < 4; it++) {
            int r = (tid >> 3) + it * 32;
            int c = (tid & 7) * 4;
            float4 v = *(const float4*)&W[(long)(co0 + r) * Cin + k0 + c];
            As[r * AST + c + 0] = f2tf(v.x);
            As[r * AST + c + 1] = f2tf(v.y);
            As[r * AST + c + 2] = f2tf(v.z);
            As[r * AST + c + 3] = f2tf(v.w);
        }
        #pragma unroll
        for (int it = 0; it < 4; it++) {
            int kk = (tid >> 5) + it * 8;
            int pp = lane * 4;
            float4 v = *(const float4*)&Xb[(long)(k0 + kk) * HW + p0 + pp];
            Bs[kk * BST + pp + 0] = f2tf(v.x);
            Bs[kk * BST + pp + 1] = f2tf(v.y);
            Bs[kk * BST + pp + 2] = f2tf(v.z);
            Bs[kk * BST + pp + 3] = f2tf(v.w);
        }
        __syncthreads();
        mma_chunk(As, Bs, wm, wn, lane, acc);
        __syncthreads();
    }

    #pragma unroll
    for (int mt = 0; mt < 4; mt++) {
        int r0 = co0 + wm * 64 + mt * 16 + (lane >> 2);
        int r1 = r0 + 8;
        float s0 = 1.f, c0 = 0.f, s1 = 1.f, c1 = 0.f;
        if (flags & 1) {
            float g0 = bn[r0], b0v = bn[Cout + r0], m0 = bn[2*Cout + r0], v0 = bn[3*Cout + r0];
            s0 = g0 * rsqrtf(v0 + 1e-3f); c0 = b0v - m0 * s0;
            float g1 = bn[r1], b1v = bn[Cout + r1], m1 = bn[2*Cout + r1], v1 = bn[3*Cout + r1];
            s1 = g1 * rsqrtf(v1 + 1e-3f); c1 = b1v - m1 * s1;
        }
        #pragma unroll
        for (int nt = 0; nt < 4; nt++) {
            int col = p0 + wn * 32 + nt * 8 + 2 * (lane & 3);
            float v00 = acc[mt][nt][0] * s0 + c0;
            float v01 = acc[mt][nt][1] * s0 + c0;
            float v10 = acc[mt][nt][2] * s1 + c1;
            float v11 = acc[mt][nt][3] * s1 + c1;
            if (flags & 2) {
                v00 = v00 / (1.f + __expf(-v00));
                v01 = v01 / (1.f + __expf(-v01));
                v10 = v10 / (1.f + __expf(-v10));
                v11 = v11 / (1.f + __expf(-v11));
            }
            if (flags & 4) {
                const float* rb = res + (long)b * rbS;
                v00 += rb[(long)r0 * HW + col];
                v01 += rb[(long)r0 * HW + col + 1];
                v10 += rb[(long)r1 * HW + col];
                v11 += rb[(long)r1 * HW + col + 1];
            }
            float* ob = out + (long)b * obS;
            *(float2*)&ob[(long)r0 * HW + col] = make_float2(v00, v01);
            *(float2*)&ob[(long)r1 * HW + col] = make_float2(v10, v11);
        }
    }
}

// ---------------------------------------------------------------------------
// Tap-split tf32 3x3 conv (unchanged from round 8).
// ---------------------------------------------------------------------------
__global__ __launch_bounds__(256) void conv3_part_kernel(
    const float* __restrict__ X, const float* __restrict__ Wt,
    float* __restrict__ part_out, long xbS)
{
    __shared__ uint32_t As[128 * AST];
    __shared__ uint32_t Bs[32 * BST];

    const int b    = blockIdx.z;
    const int p0   = blockIdx.x * 128;
    const int part = blockIdx.y >> 1;
    const int co0  = (blockIdx.y & 1) * 128;
    const int tid  = threadIdx.x;
    const int lane = tid & 31, wid = tid >> 5;
    const int wm = wid >> 2, wn = wid & 3;

    const float* Xb = X + (long)b * xbS;

    float acc[4][4][4];
    #pragma unroll
    for (int mt = 0; mt < 4; mt++)
        #pragma unroll
        for (int nt = 0; nt < 4; nt++)
            #pragma unroll
            for (int e = 0; e < 4; e++) acc[mt][nt][e] = 0.f;

    for (int c = 0; c < 24; c++) {
        const int t  = part * 3 + (c >> 3);
        const int kc = (c & 7) * 32;
        const int dy = t / 3 - 1, dx = t % 3 - 1;
        const float* Wtt = Wt + t * 65536;

        #pragma unroll
        for (int it = 0; it < 4; it++) {
            int r = (tid >> 3) + it * 32;
            int cc = (tid & 7) * 4;
            float4 v = *(const float4*)&Wtt[(long)(co0 + r) * 256 + kc + cc];
            As[r * AST + cc + 0] = f2tf(v.x);
            As[r * AST + cc + 1] = f2tf(v.y);
            As[r * AST + cc + 2] = f2tf(v.z);
            As[r * AST + cc + 3] = f2tf(v.w);
        }
        #pragma unroll
        for (int e = tid; e < 4096; e += 256) {
            int kk = e >> 7, p = e & 127;
            int pix = p0 + p;
            int row = (pix >> 5) + dy;
            int col = (pix & 31) + dx;
            float xv = 0.f;
            if ((unsigned)row < 32u && (unsigned)col < 32u)
                xv = Xb[(long)(kc + kk) * HW + row * 32 + col];
            Bs[kk * BST + p] = f2tf(xv);
        }
        __syncthreads();
        mma_chunk(As, Bs, wm, wn, lane, acc);
        __syncthreads();
    }

    float* ob = part_out + ((long)part * BATCH + b) * 256 * HW;
    #pragma unroll
    for (int mt = 0; mt < 4; mt++) {
        int r0 = co0 + wm * 64 + mt * 16 + (lane >> 2);
        int r1 = r0 + 8;
        #pragma unroll
        for (int nt = 0; nt < 4; nt++) {
            int col = p0 + wn * 32 + nt * 8 + 2 * (lane & 3);
            *(float2*)&ob[(long)r0 * HW + col] =
                make_float2(acc[mt][nt][0], acc[mt][nt][1]);
            *(float2*)&ob[(long)r1 * HW + col] =
                make_float2(acc[mt][nt][2], acc[mt][nt][3]);
        }
    }
}

// ---------------------------------------------------------------------------
__global__ void tap_reduce_kernel(const float* __restrict__ part,
                                  const float* __restrict__ bn,
                                  float* __restrict__ out)
{
    const long PS = (long)BATCH * 256 * HW;
    long idx = (long)blockIdx.x * 256 + threadIdx.x;
    if (idx >= PS / 4) return;
    long e = idx * 4;
    int ch = (int)((e / HW) & 255);

    float4 a = *(const float4*)&part[e];
    float4 b4 = *(const float4*)&part[PS + e];
    float4 c4 = *(const float4*)&part[2 * PS + e];

    float g = bn[ch], bb = bn[256 + ch], mu = bn[512 + ch], vv = bn[768 + ch];
    float s = g * rsqrtf(vv + 1e-3f);
    float c = bb - mu * s;

    float v[4] = {a.x + b4.x + c4.x, a.y + b4.y + c4.y,
                  a.z + b4.z + c4.z, a.w + b4.w + c4.w};
    #pragma unroll
    for (int i = 0; i < 4; i++) {
        float t = v[i] * s + c;
        v[i] = t / (1.f + __expf(-t));
    }
    *(float4*)&out[e] = make_float4(v[0], v[1], v[2], v[3]);
}

// ---------------------------------------------------------------------------
// Pack qkv: fp32 -> tf32 bits; add rw+rh positional bias to K channels.
// Streaming elementwise, float4. Channels: [0,256) Q, [256,512) K, [512,768) V.
// ---------------------------------------------------------------------------
__global__ void qkv_pack_kernel(const float* __restrict__ in,
                                const float* __restrict__ rw,
                                const float* __restrict__ rh,
                                float* __restrict__ outp)
{
    const long N4 = (long)BATCH * 768 * HW / 4;
    long idx = (long)blockIdx.x * 256 + threadIdx.x;
    if (idx >= N4) return;
    long e = idx * 4;
    int ch = (int)((e / HW) % 768);
    int p  = (int)(e & (HW - 1));

    float4 v = *(const float4*)&in[e];
    float f[4] = {v.x, v.y, v.z, v.w};

    if (ch >= 256 && ch < 512) {
        int hd  = ch - 256;                 // h*64 + d
        int col = p & 31, row = p >> 5;     // p%4==0 -> same row for all 4
        const float* rwp = rw + hd * 32;
        float rhv = rh[hd * 32 + row];
        #pragma unroll
        for (int i = 0; i < 4; i++)
            f[i] += rwp[col + i] + rhv;
    }

    uint4 o;
    o.x = f2tf(f[0]); o.y = f2tf(f[1]); o.z = f2tf(f[2]); o.w = f2tf(f[3]);
    *(uint4*)&outp[e] = o;
}

// ---------------------------------------------------------------------------
// tf32 flash attention: qkvp holds pre-converted tf32 bits, bias already in K.
// Fills are pure uint4 bit-copies.
// ---------------------------------------------------------------------------
#define QST 72
#define VST 68
#define FA_Q   0
#define FA_KR  (64 * QST)
#define FA_V   (FA_KR + 64 * QST)
#define FA_P   (FA_V + 64 * VST)
#define FA_RED (FA_P + 64 * VST)
#define FA_TOT (FA_RED + 256)

extern __shared__ uint32_t fa_u[];

__global__ __launch_bounds__(256) void flash_tf32_kernel(
    const uint32_t* __restrict__ qkv, float* __restrict__ out)
{
    uint32_t* Qs  = fa_u + FA_Q;
    uint32_t* KRs = fa_u + FA_KR;
    uint32_t* Vs  = fa_u + FA_V;
    uint32_t* Ps  = fa_u + FA_P;
    float* red_max = (float*)(fa_u + FA_RED);
    float* red_sum = red_max + 128;

    const int b  = blockIdx.z;
    const int h  = blockIdx.y;
    const int i0 = blockIdx.x * 64;
    const int tid  = threadIdx.x;
    const int lane = tid & 31, wid = tid >> 5;
    const int wm = wid >> 1;
    const int wn = wid & 1;
    const int lq = lane >> 2;
    const int lr = lane & 3;

    const uint32_t* qb = qkv + ((long)b * 768 + h * 64) * HW;
    const uint32_t* kb = qb + 256 * HW;
    const uint32_t* vb = qb + 512 * HW;

    #pragma unroll
    for (int it = 0; it < 4; it++) {
        int idx = tid + it * 256;
        int d = idx >> 4, i4 = (idx & 15) * 4;
        *(uint4*)&Qs[d * QST + i4] = *(const uint4*)&qb[(long)d * HW + i0 + i4];
    }

    const int row_lo = wm * 16 + lq;
    const int row_hi = row_lo + 8;

    float m_lo = -1e30f, m_hi = -1e30f, l_lo = 0.f, l_hi = 0.f;
    float accO[4][4];
    #pragma unroll
    for (int nt = 0; nt < 4; nt++)
        #pragma unroll
        for (int e = 0; e < 4; e++) accO[nt][e] = 0.f;

    __syncthreads();

    for (int j0 = 0; j0 < HW; j0 += 64) {
        #pragma unroll
        for (int it = 0; it < 4; it++) {
            int idx = tid + it * 256;
            int d = idx >> 4, j4 = (idx & 15) * 4;
            *(uint4*)&KRs[d * QST + j4] = *(const uint4*)&kb[(long)d * HW + j0 + j4];
            *(uint4*)&Vs[d * VST + j4]  = *(const uint4*)&vb[(long)d * HW + j0 + j4];
        }
        __syncthreads();

        float s[4][4];
        #pragma unroll
        for (int nt = 0; nt < 4; nt++)
            #pragma unroll
            for (int e = 0; e < 4; e++) s[nt][e] = 0.f;

        #pragma unroll
        for (int ks = 0; ks < 8; ks++) {
            int d0 = ks * 8 + lr;
            uint32_t a0 = Qs[d0 * QST + row_lo];
            uint32_t a1 = Qs[d0 * QST + row_hi];
            uint32_t a2 = Qs[(d0 + 4) * QST + row_lo];
            uint32_t a3 = Qs[(d0 + 4) * QST + row_hi];
            #pragma unroll
            for (int nt = 0; nt < 4; nt++) {
                int jc = wn * 32 + nt * 8 + lq;
                uint32_t b0 = KRs[d0 * QST + jc];
                uint32_t b1 = KRs[(d0 + 4) * QST + jc];
                mma8(s[nt], a0, a1, a2, a3, b0, b1);
            }
        }

        #pragma unroll
        for (int nt = 0; nt < 4; nt++)
            #pragma unroll
            for (int e = 0; e < 4; e++) s[nt][e] *= 0.125f;

        float mx_lo = -1e30f, mx_hi = -1e30f;
        #pragma unroll
        for (int nt = 0; nt < 4; nt++) {
            mx_lo = fmaxf(mx_lo, fmaxf(s[nt][0], s[nt][1]));
            mx_hi = fmaxf(mx_hi, fmaxf(s[nt][2], s[nt][3]));
        }
        mx_lo = fmaxf(mx_lo, __shfl_xor_sync(0xffffffffu, mx_lo, 1));
        mx_lo = fmaxf(mx_lo, __shfl_xor_sync(0xffffffffu, mx_lo, 2));
        mx_hi = fmaxf(mx_hi, __shfl_xor_sync(0xffffffffu, mx_hi, 1));
        mx_hi = fmaxf(mx_hi, __shfl_xor_sync(0xffffffffu, mx_hi, 2));
        if (lr == 0) {
            red_max[wn * 64 + row_lo] = mx_lo;
            red_max[wn * 64 + row_hi] = mx_hi;
        }
        __syncthreads();
        mx_lo = fmaxf(mx_lo, red_max[(1 - wn) * 64 + row_lo]);
        mx_hi = fmaxf(mx_hi, red_max[(1 - wn) * 64 + row_hi]);

        float mn_lo = fmaxf(m_lo, mx_lo);
        float mn_hi = fmaxf(m_hi, mx_hi);
        float cr_lo = __expf(m_lo - mn_lo);
        float cr_hi = __expf(m_hi - mn_hi);
        m_lo = mn_lo; m_hi = mn_hi;

        float rs_lo = 0.f, rs_hi = 0.f;
        #pragma unroll
        for (int nt = 0; nt < 4; nt++) {
            float p0 = __expf(s[nt][0] - mn_lo);
            float p1 = __expf(s[nt][1] - mn_lo);
            float p2 = __expf(s[nt][2] - mn_hi);
            float p3 = __expf(s[nt][3] - mn_hi);
            rs_lo += p0 + p1;
            rs_hi += p2 + p3;
            int colb = wn * 32 + nt * 8 + 2 * lr;
            *(uint2*)&Ps[row_lo * VST + colb] = make_uint2(f2tf(p0), f2tf(p1));
            *(uint2*)&Ps[row_hi * VST + colb] = make_uint2(f2tf(p2), f2tf(p3));
        }
        rs_lo += __shfl_xor_sync(0xffffffffu, rs_lo, 1);
        rs_lo += __shfl_xor_sync(0xffffffffu, rs_lo, 2);
        rs_hi += __shfl_xor_sync(0xffffffffu, rs_hi, 1);
        rs_hi += __shfl_xor_sync(0xffffffffu, rs_hi, 2);
        if (lr == 0) {
            red_sum[wn * 64 + row_lo] = rs_lo;
            red_sum[wn * 64 + row_hi] = rs_hi;
        }
        __syncthreads();
        rs_lo += red_sum[(1 - wn) * 64 + row_lo];
        rs_hi += red_sum[(1 - wn) * 64 + row_hi];
        l_lo = l_lo * cr_lo + rs_lo;
        l_hi = l_hi * cr_hi + rs_hi;

        #pragma unroll
        for (int nt = 0; nt < 4; nt++) {
            accO[nt][0] *= cr_lo; accO[nt][1] *= cr_lo;
            accO[nt][2] *= cr_hi; accO[nt][3] *= cr_hi;
        }

        #pragma unroll
        for (int ks = 0; ks < 8; ks++) {
            int jj = ks * 8 + lr;
            uint32_t a0 = Ps[row_lo * VST + jj];
            uint32_t a1 = Ps[row_hi * VST + jj];
            uint32_t a2 = Ps[row_lo * VST + jj + 4];
            uint32_t a3 = Ps[row_hi * VST + jj + 4];
            #pragma unroll
            for (int nt = 0; nt < 4; nt++) {
                int dc = wn * 32 + nt * 8 + lq;
                uint32_t b0 = Vs[dc * VST + jj];
                uint32_t b1 = Vs[dc * VST + jj + 4];
                mma8(accO[nt], a0, a1, a2, a3, b0, b1);
            }
        }
        __syncthreads();
    }

    float inv_lo = 1.f / l_lo;
    float inv_hi = 1.f / l_hi;
    float* ob = out + ((long)b * 256 + h * 64) * HW + i0;
    #pragma unroll
    for (int nt = 0; nt < 4; nt++) {
        int d = wn * 32 + nt * 8 + 2 * lr;
        ob[(long)d * HW + row_lo]       = accO[nt][0] * inv_lo;
        ob[(long)(d + 1) * HW + row_lo] = accO[nt][1] * inv_lo;
        ob[(long)d * HW + row_hi]       = accO[nt][2] * inv_hi;
        ob[(long)(d + 1) * HW + row_hi] = accO[nt][3] * inv_hi;
    }
}

// ---------------------------------------------------------------------------
extern "C" void kernel_launch(void* const* d_in, const int* in_sizes, int n_in,
                              void* d_out, int out_size)
{
    const float* x        = (const float*)d_in[0];
    const float* cv1_w    = (const float*)d_in[1];
    const float* cv1_bn   = (const float*)d_in[2];
    const float* cv2_w    = (const float*)d_in[3];
    const float* cv2_bn   = (const float*)d_in[4];
    const float* m_cv1_w  = (const float*)d_in[5];
    const float* m_cv1_bn = (const float*)d_in[6];
    const float* m_qkv_w  = (const float*)d_in[7];
    const float* m_rw     = (const float*)d_in[8];
    const float* m_rh     = (const float*)d_in[9];
    const float* m_cv2_w  = (const float*)d_in[10];
    const float* m_cv2_bn = (const float*)d_in[11];
    float* out = (float*)d_out;

    float *cat, *z, *qkv, *qkvp, *att, *w3, *part;
    cudaGetSymbolAddress((void**)&cat,  g_cat);
    cudaGetSymbolAddress((void**)&z,    g_z);
    cudaGetSymbolAddress((void**)&qkv,  g_qkv);
    cudaGetSymbolAddress((void**)&qkvp, g_qkvp);
    cudaGetSymbolAddress((void**)&att,  g_att);
    cudaGetSymbolAddress((void**)&w3,   g_w3);
    cudaGetSymbolAddress((void**)&part, g_part);

    const int FA_SMEM = FA_TOT * 4;
    cudaFuncSetAttribute(flash_tf32_kernel,
                         cudaFuncAttributeMaxDynamicSharedMemorySize, FA_SMEM);

    const long CAT_S = 1024L * HW;
    const long RED_N  = (long)BATCH * 256 * HW / 4;
    const long PACK_N = (long)BATCH * 768 * HW / 4;

    reorder_w3_kernel<<<(2 * 9 * 65536 + 255) / 256, 256>>>(m_cv1_w, w3);

    // cv1: x (512) -> cat[0:512)
    gemm_tf32_kernel<<<dim3(8, 4, BATCH), 256>>>(
        x, cv1_w, cv1_bn, nullptr, cat,
        512, 512, 512L * HW, CAT_S, 0, 3);

    for (int i = 0; i < 2; i++) {
        const float* yin = cat + (long)(256 + i * 256) * HW;

        conv3_part_kernel<<<dim3(8, 6, BATCH), 256>>>(
            yin, w3 + (long)i * 9 * 65536, part, CAT_S);
        tap_reduce_kernel<<<(int)((RED_N + 255) / 256), 256>>>(
            part, m_cv1_bn + i * 4 * 256, z);

        // qkv 1x1 (plain fp32 output)
        gemm_tf32_kernel<<<dim3(8, 6, BATCH), 256>>>(
            z, m_qkv_w + (long)i * 768 * 256, nullptr, nullptr, qkv,
            256, 768, 256L * HW, 768L * HW, 0, 0);

        // pack to tf32 bits, fold rw+rh bias into K
        qkv_pack_kernel<<<(int)((PACK_N + 255) / 256), 256>>>(
            qkv, m_rw + i * 8192, m_rh + i * 8192, qkvp);

        flash_tf32_kernel<<<dim3(16, 4, BATCH), 256, FA_SMEM>>>(
            (const uint32_t*)qkvp, att);

        gemm_tf32_kernel<<<dim3(8, 2, BATCH), 256>>>(
            att, m_cv2_w + (long)i * 256 * 256, m_cv2_bn + i * 4 * 256,
            yin, cat + (long)(512 + i * 256) * HW,
            256, 256, 256L * HW, CAT_S, CAT_S, 7);
    }

    gemm_tf32_kernel<<<dim3(8, 4, BATCH), 256>>>(
        cat, cv2_w, cv2_bn, nullptr, out,
        1024, 512, CAT_S, 512L * HW, 0, 3);
}